// round 15
// baseline (speedup 1.0000x reference)
#include <cuda_runtime.h>
#include <cuda_fp16.h>
#include <math.h>
#include <stdint.h>

#define HD    1024
#define KH    8
#define BATCH 8192
#define EPSLN 1e-5f

// ---------------- scratch (static device globals; no allocs allowed) --------
static __device__ float    g_y1 [(size_t)BATCH * 2 * HD];        //  64 MB G1 out -> h in place
static __device__ float    g_xe [(size_t)BATCH * HD];            //  32 MB GX out
static __device__ float    g_e  [(size_t)BATCH * KH * HD];       // 256 MB G3 out (permuted rows)
static __device__ uint32_t g_wAs [(size_t)24 * 32 * 4096];       //  12.6 MB W1^T + We1-top tiles
static __device__ uint32_t g_w2s [(size_t)2 * HD * KH * HD];     //  64 MB W2^T split tiles
static __device__ uint32_t g_we1b[(size_t)HD * HD];              //   4 MB We1-bottom tiles

// ============================ PTX helpers (portable, sm_80+) =================
__device__ __forceinline__ uint32_t smem_u32(const void* p) {
    uint32_t a;
    asm("{ .reg .u64 t; cvta.to.shared.u64 t, %1; cvt.u32.u64 %0, t; }" : "=r"(a) : "l"(p));
    return a;
}
__device__ __forceinline__ void cp_async16(uint32_t saddr, const void* g) {
    asm volatile("cp.async.cg.shared.global [%0], [%1], 16;" :: "r"(saddr), "l"(g));
}
__device__ __forceinline__ void cp_commit() {
    asm volatile("cp.async.commit_group;" ::: "memory");
}
template<int N> __device__ __forceinline__ void cp_wait() {
    asm volatile("cp.async.wait_group %0;" :: "n"(N) : "memory");
}
// fp16 error-compensated split of a pair of fp32 values -> hi word, lo word
__device__ __forceinline__ void split2h(float v0, float v1, uint32_t& hw, uint32_t& lw) {
    __half2 h = __floats2half2_rn(v0, v1);
    float2 hf = __half22float2(h);
    __half2 l = __floats2half2_rn(v0 - hf.x, v1 - hf.y);
    hw = *(uint32_t*)&h;
    lw = *(uint32_t*)&l;
}
__device__ __forceinline__ void mma16(float* c, const uint32_t* a, const uint32_t* b) {
    asm volatile(
        "mma.sync.aligned.m16n8k16.row.col.f32.f16.f16.f32 "
        "{%0,%1,%2,%3}, {%4,%5,%6,%7}, {%8,%9}, {%0,%1,%2,%3};"
        : "+f"(c[0]), "+f"(c[1]), "+f"(c[2]), "+f"(c[3])
        : "r"(a[0]), "r"(a[1]), "r"(a[2]), "r"(a[3]), "r"(b[0]), "r"(b[1]));
}

// A fragment load from smem (additive swizzle slot = r*16 + ((p + 4r) & 15))
__device__ __forceinline__ void lds_a8(const float2* __restrict__ sAf,
                                       int wm, int g, int tg, int kb, float2 ar[2][4]) {
    #pragma unroll
    for (int mt = 0; mt < 2; mt++) {
        const int r0 = wm * 32 + mt * 16 + g;
        const int r1 = r0 + 8;
        const int p0 = kb * 8 + tg, p1 = p0 + 4;
        ar[mt][0] = sAf[r0 * 16 + ((p0 + r0 * 4) & 15)];
        ar[mt][1] = sAf[r1 * 16 + ((p0 + r1 * 4) & 15)];
        ar[mt][2] = sAf[r0 * 16 + ((p1 + r0 * 4) & 15)];
        ar[mt][3] = sAf[r1 * 16 + ((p1 + r1 * 4) & 15)];
    }
}

// A fragment load from GLOBAL: 8 LDG.64, rows wm/g, cols k..k+15.
// Lane quad (tg) covers 32B contiguous per row -> full sector efficiency.
__device__ __forceinline__ void ldg_a8(const float* __restrict__ base, int lda, int k,
                                       int wm, int g, int tg, float2 ar[2][4]) {
    #pragma unroll
    for (int mt = 0; mt < 2; mt++) {
        const int r0 = wm * 32 + mt * 16 + g;
        const float* p0 = base + (size_t)r0 * lda + k + tg * 2;
        const float* p1 = p0 + (size_t)8 * lda;
        ar[mt][0] = *(const float2*)p0;
        ar[mt][1] = *(const float2*)p1;
        ar[mt][2] = *(const float2*)(p0 + 8);
        ar[mt][3] = *(const float2*)(p1 + 8);
    }
}

// ============================ fp16x3 GEMM =====================================
// C[M,N] = A @ B^T.  A: plain fp32 row-major; kb1 fragments via cp.async->smem
// ->LDS (current stage, always resident), tile-CROSSING kb0 fragments via LDG
// from global (issued at kb1 start, covered by kb1's MMA phase; A is L2-
// resident). This removes the early-stage dependency, so the cp.async ring
// runs at cp_wait<1> depth (2 tiles of flight per stage). B: pre-split weight
// tiles (128x32k = 4096 words). CTA 128x128, 8 warps 4x2, BK=32/stage,
// 3-stage ring (96 KB), 2 CTAs/SM, 16-wide grid swizzle.
// 3 MMA passes: hi*lo + lo*hi + hi*hi (bit-identical to R8..R14).
// MODE 0: +bias[n].
// MODE 1: dual output: bn < N -> C (+aux), bn >= N -> C2 (+aux2), width N2.
// MODE 2: A rows permuted from hyps (r = kk*8192+b), +aux[(row&8191)*N + n].
#define SMEM_DYN (3 * 32 * 1024)

template<int MODE>
__global__ void __launch_bounds__(256, 2) mma_gemm(
    const float* __restrict__ A, int lda,
    const uint32_t* __restrict__ Bt, int nBk, int koff, int ntk,  // ntk = # 32k tiles
    const float* __restrict__ aux, float* __restrict__ C, int N,
    const float* __restrict__ aux2, float* __restrict__ C2, int N2)
{
    extern __shared__ uint32_t smu[];        // 3 stages x 8192 words (A 4096 | B 4096)
    const int tid  = threadIdx.x;
    const int lane = tid & 31, wid = tid >> 5;
    const int wm = wid & 3, wn = wid >> 2;
    const int g = lane >> 2, tg = lane & 3;
    const int sx = (g & 2) << 1;             // B-side XOR swizzle term

    // grid swizzle: waves cover ~16 m-blocks x ~N n-blocks (L2 locality)
    const int GM = gridDim.x, GN = gridDim.y;
    const int L = blockIdx.x + blockIdx.y * GM;
    const int chunk = L >> 4;
    const int nb = chunk % GN;
    const int mb = (chunk / GN) * 16 + (L & 15);
    const int bm = mb * 128, bn = nb * 128;

    float acc[2][8][4];
    #pragma unroll
    for (int mt = 0; mt < 2; mt++)
        #pragma unroll
        for (int nt = 0; nt < 8; nt++)
            #pragma unroll
            for (int i = 0; i < 4; i++) acc[mt][nt][i] = 0.f;

    // A base: MODE 2 maps GEMM row r = kk*8192 + b onto hyps[b][kk*HD + .]
    const float* Abase;
    if (MODE == 2) {
        const int kk = mb >> 6, b0 = (mb & 63) * 128;
        Abase = A + (size_t)b0 * lda + kk * HD;
    } else {
        Abase = A + (size_t)bm * lda;
    }
    const uint32_t* Bb = Bt + ((size_t)nb * nBk + koff) * 4096 + tid * 4;

    auto load_stage = [&](int t, int buf) {
        const int k0 = t * 32;
        const uint32_t dA = smem_u32(&smu[buf * 8192]);
        #pragma unroll
        for (int i = 0; i < 4; i++) {        // A: 1024 x 16B chunks
            int c = tid + i * 256;
            int row = c >> 3, cp = c & 7;
            int slot = row * 16 + (((cp << 1) + (row << 2)) & 15);
            cp_async16(dA + slot * 8, Abase + (size_t)row * lda + k0 + cp * 4);
        }
        const uint32_t dB = smem_u32(&smu[buf * 8192 + 4096 + tid * 4]);
        const uint32_t* b = Bb + (size_t)t * 4096;
        #pragma unroll
        for (int i = 0; i < 4; i++) cp_async16(dB + i * 4096, b + i * 1024);
    };

    load_stage(0, 0); cp_commit();
    if (ntk > 1) { load_stage(1, 1); cp_commit(); }

    float2 ar[2][4];
    ldg_a8(Abase, lda, 0, wm, g, tg, ar);    // prime: tile 0 kb0 straight from global

    for (int it = 0; it < ntk; it++) {
        cp_wait<1>();                         // stage `it` resident (2-tile flight)
        __syncthreads();
        if (it + 2 < ntk) load_stage(it + 2, (it + 2) % 3);
        cp_commit();                          // unconditional: keeps group counting uniform

        const float2*   sAc = (const float2*)&smu[(it % 3) * 8192];
        const uint32_t* sB  = &smu[(it % 3) * 8192 + 4096];

        #pragma unroll
        for (int kb = 0; kb < 2; kb++) {
            // split the pre-loaded fragment, then fetch the next one
            uint32_t aH[2][4], aL[2][4];
            #pragma unroll
            for (int mt = 0; mt < 2; mt++)
                #pragma unroll
                for (int i = 0; i < 4; i++)
                    split2h(ar[mt][i].x, ar[mt][i].y, aH[mt][i], aL[mt][i]);
            if (kb == 0) {
                lds_a8(sAc, wm, g, tg, 1, ar);            // this tile kb1 (smem)
            } else {
                int kn = (it + 1 < ntk) ? (it + 1) * 32 : 0;  // clamp: dummy on last
                ldg_a8(Abase, lda, kn, wm, g, tg, ar);    // next tile kb0 (global)
            }

            const uint32_t* Bk = sB + kb * 2048;
            #pragma unroll
            for (int nh = 0; nh < 2; nh++) {
                uint32_t bH[4][2], bL[4][2];
                #pragma unroll
                for (int q = 0; q < 4; q++) {
                    const int n = wn * 64 + (nh * 4 + q) * 8 + g;
                    uint2 u0 = *(const uint2*)(Bk + (n * 8 + (tg ^ sx)) * 2);
                    uint2 u1 = *(const uint2*)(Bk + (n * 8 + ((tg + 4) ^ sx)) * 2);
                    bH[q][0] = u0.x; bH[q][1] = u1.x;
                    bL[q][0] = u0.y; bL[q][1] = u1.y;
                }
                float* a0 = &acc[0][nh * 4][0];
                float* a1 = &acc[1][nh * 4][0];
                #pragma unroll
                for (int q = 0; q < 4; q++) { mma16(a0 + q * 4, aH[0], bL[q]); mma16(a1 + q * 4, aH[1], bL[q]); }
                #pragma unroll
                for (int q = 0; q < 4; q++) { mma16(a0 + q * 4, aL[0], bH[q]); mma16(a1 + q * 4, aL[1], bH[q]); }
                #pragma unroll
                for (int q = 0; q < 4; q++) { mma16(a0 + q * 4, aH[0], bH[q]); mma16(a1 + q * 4, aH[1], bH[q]); }
            }
        }
    }

    // ---------------- epilogue --------------------------------------------
    float* Cp = C;
    const float* ax = aux;
    int Nn = N, cb = bn;
    if (MODE == 1 && bn >= N) { Cp = C2; ax = aux2; Nn = N2; cb = bn - N; }

    #pragma unroll
    for (int mt = 0; mt < 2; mt++) {
        const int row0 = bm + wm * 32 + mt * 16 + g;
        #pragma unroll
        for (int nt = 0; nt < 8; nt++) {
            const int col = cb + wn * 64 + nt * 8 + 2 * tg;
            float o0 = acc[mt][nt][0], o1 = acc[mt][nt][1];
            float o2 = acc[mt][nt][2], o3 = acc[mt][nt][3];
            if (MODE != 2) {
                float z0 = ax[col], z1 = ax[col + 1];
                o0 += z0; o1 += z1; o2 += z0; o3 += z1;
            } else {
                const float* a0 = aux + (size_t)(row0 & (BATCH - 1)) * Nn + col;
                const float* a1 = aux + (size_t)((row0 + 8) & (BATCH - 1)) * Nn + col;
                o0 += a0[0]; o1 += a0[1]; o2 += a1[0]; o3 += a1[1];
            }
            *(float2*)(Cp + (size_t)row0 * Nn + col)       = make_float2(o0, o1);
            *(float2*)(Cp + (size_t)(row0 + 8) * Nn + col) = make_float2(o2, o3);
        }
    }
}

// ================= one-time weight transpose+split+tile ======================
// W [K][N] row-major -> B-split tiles [nblk][ktile], grid = (N/128, K/32).
// Tile format: word pair for (n-row, k even):
//   idx = kb*2048 + (n*8 + k2s)*2, k2s = ((k>>1)&7) ^ ((n&2)<<1);
//   [idx] = {hi(k),hi(k+1)}, [idx+1] = {lo(k),lo(k+1)}.
__global__ void __launch_bounds__(256) wsplit_kernel(
    const float* __restrict__ W, uint32_t* __restrict__ out, int N)
{
    __shared__ float s[32 * 132];
    const int t = threadIdx.x;
    #pragma unroll
    for (int i = 0; i < 16; i++) {
        int e = t + i * 256;
        int kl = e >> 7, nl = e & 127;
        s[kl * 132 + nl] = W[(size_t)(blockIdx.y * 32 + kl) * N + blockIdx.x * 128 + nl];
    }
    __syncthreads();
    uint32_t* ob = out + ((size_t)blockIdx.x * gridDim.y + blockIdx.y) * 4096;
    #pragma unroll
    for (int i = 0; i < 16; i++) {
        int o = t + i * 256;                 // word index in tile
        int w = o & 1, q = o >> 1;           // q = kb*1024 + nl*8 + k2s
        int kb = q >> 10, r = q & 1023;
        int nl = r >> 3, k2s = r & 7;
        int k2 = k2s ^ ((nl & 2) << 1);
        int k = kb * 16 + k2 * 2;
        uint32_t hw, lw;
        split2h(s[k * 132 + nl], s[(k + 1) * 132 + nl], hw, lw);
        ob[o] = w ? lw : hw;
    }
}

// ---------------- block reduction of two scalars (256 threads) --------------
__device__ __forceinline__ void block_reduce2(float& a, float& b) {
    __shared__ float sa[8], sb[8];
    float x = a, y = b;
    #pragma unroll
    for (int o = 16; o > 0; o >>= 1) {
        x += __shfl_down_sync(0xffffffffu, x, o);
        y += __shfl_down_sync(0xffffffffu, y, o);
    }
    int w = threadIdx.x >> 5;
    if ((threadIdx.x & 31) == 0) { sa[w] = x; sb[w] = y; }
    __syncthreads();
    if (threadIdx.x == 0) {
        float xs = 0.f, ys = 0.f;
        #pragma unroll
        for (int i = 0; i < 8; i++) { xs += sa[i]; ys += sb[i]; }
        sa[0] = xs; sb[0] = ys;
    }
    __syncthreads();
    a = sa[0]; b = sb[0];
    __syncthreads();
}

// -------- LN + ReLU over width 2048, in place (h overwrites y1) -------------
__global__ void __launch_bounds__(256) ln_relu_2048(
    float* __restrict__ y, const float* __restrict__ g, const float* __restrict__ beta)
{
    const int row = blockIdx.x;
    float* p = y + (size_t)row * 2048;
    const int j0 = threadIdx.x * 8;
    float v[8];
    *(float4*)&v[0] = *(const float4*)(p + j0);
    *(float4*)&v[4] = *(const float4*)(p + j0 + 4);
    float s = 0.f, ss = 0.f;
    #pragma unroll
    for (int i = 0; i < 8; i++) { s += v[i]; ss += v[i] * v[i]; }
    block_reduce2(s, ss);
    const float mean = s * (1.f / 2048.f);
    const float var  = ss * (1.f / 2048.f) - mean * mean;
    const float rs   = rsqrtf(var + EPSLN);
    float o[8];
    #pragma unroll
    for (int i = 0; i < 8; i++) {
        int j = j0 + i;
        o[i] = fmaxf((v[i] - mean) * rs * g[j] + beta[j], 0.f);
    }
    *(float4*)(p + j0)     = *(float4*)&o[0];
    *(float4*)(p + j0 + 4) = *(float4*)&o[4];
}

// ---------------- per permuted row: LN + ReLU + dot(We2) + sigmoid ----------
__global__ void __launch_bounds__(256) score_kernel(
    const float* __restrict__ e, const float* __restrict__ ge,
    const float* __restrict__ betae, const float* __restrict__ We2,
    const float* __restrict__ be2, float* __restrict__ scores)
{
    const int r = blockIdx.x;               // r = k*8192 + b
    const float* p = e + (size_t)r * HD;
    const int t = threadIdx.x;
    float v[4];
    float s = 0.f, ss = 0.f;
    #pragma unroll
    for (int i = 0; i < 4; i++) {
        v[i] = p[t + i * 256];
        s += v[i]; ss += v[i] * v[i];
    }
    block_reduce2(s, ss);
    const float mean = s * (1.f / 1024.f);
    const float var  = ss * (1.f / 1024.f) - mean * mean;
    const float rs   = rsqrtf(var + EPSLN);
    float d = 0.f, dummy = 0.f;
    #pragma unroll
    for (int i = 0; i < 4; i++) {
        int j = t + i * 256;
        float o = fmaxf((v[i] - mean) * rs * ge[j] + betae[j], 0.f);
        d = fmaf(o, We2[j], d);
    }
    block_reduce2(d, dummy);
    if (t == 0) {
        int b = r & (BATCH - 1), k = r >> 13;
        scores[(size_t)b * KH + k] = 1.f / (1.f + expf(-(d + be2[0])));
    }
}

// ---------------- argmax over K, gather best hypothesis ---------------------
__global__ void __launch_bounds__(256) finalize_kernel(
    const float* __restrict__ scores, const float* __restrict__ hyps,
    float* __restrict__ best_hyp, float* __restrict__ best_idx,
    float* __restrict__ best_sc)
{
    const int b = blockIdx.x;
    __shared__ int sidx;
    if (threadIdx.x == 0) {
        const float* sc = scores + (size_t)b * KH;
        int bi = 0; float bv = sc[0];
        #pragma unroll
        for (int k = 1; k < KH; k++)
            if (sc[k] > bv) { bv = sc[k]; bi = k; }
        sidx = bi;
        best_idx[b] = (float)bi;
        best_sc[b]  = bv;
    }
    __syncthreads();
    // bit-exact float4 gather copy (rows are 4 KB aligned)
    const float4* src = (const float4*)(hyps + ((size_t)b * KH + sidx) * HD);
    float4* dst = (float4*)(best_hyp + (size_t)b * HD);
    dst[threadIdx.x] = src[threadIdx.x];     // 256 threads x 16 B = 4 KB row
}

// ---------------- launcher ---------------------------------------------------
extern "C" void kernel_launch(void* const* d_in, const int* in_sizes, int n_in,
                              void* d_out, int out_size)
{
    const float* x     = (const float*)d_in[0];
    const float* W1    = (const float*)d_in[1];
    const float* b1    = (const float*)d_in[2];
    const float* g1    = (const float*)d_in[3];
    const float* beta1 = (const float*)d_in[4];
    const float* W2    = (const float*)d_in[5];
    const float* b2    = (const float*)d_in[6];
    const float* We1   = (const float*)d_in[7];
    const float* be1   = (const float*)d_in[8];
    const float* ge    = (const float*)d_in[9];
    const float* betae = (const float*)d_in[10];
    const float* We2   = (const float*)d_in[11];
    const float* be2   = (const float*)d_in[12];

    float* out = (float*)d_out;
    float* out_best_hyp = out;                                    // [B, H]
    float* out_hyps     = out + (size_t)BATCH * HD;               // [B, K, H]
    float* out_scores   = out_hyps + (size_t)BATCH * KH * HD;     // [B, K]
    float* out_best_idx = out_scores + (size_t)BATCH * KH;        // [B, 1]
    float* out_best_sc  = out_best_idx + BATCH;                   // [B, 1]

    float *y1, *xe, *e;
    uint32_t *wAs, *w2s, *we1b;
    cudaGetSymbolAddress((void**)&y1,   g_y1);
    cudaGetSymbolAddress((void**)&xe,   g_xe);
    cudaGetSymbolAddress((void**)&e,    g_e);
    cudaGetSymbolAddress((void**)&wAs,  g_wAs);
    cudaGetSymbolAddress((void**)&w2s,  g_w2s);
    cudaGetSymbolAddress((void**)&we1b, g_we1b);

    cudaFuncSetAttribute(mma_gemm<0>, cudaFuncAttributeMaxDynamicSharedMemorySize, SMEM_DYN);
    cudaFuncSetAttribute(mma_gemm<1>, cudaFuncAttributeMaxDynamicSharedMemorySize, SMEM_DYN);
    cudaFuncSetAttribute(mma_gemm<2>, cudaFuncAttributeMaxDynamicSharedMemorySize, SMEM_DYN);

    // weight split tiles
    wsplit_kernel<<<dim3(16, 32), 256>>>(W1, wAs, 2 * HD);                       // nb 0..15
    wsplit_kernel<<<dim3(8, 32),  256>>>(We1, wAs + (size_t)16 * 32 * 4096, HD); // nb 16..23 (top)
    wsplit_kernel<<<dim3(8, 32),  256>>>(We1 + (size_t)HD * HD, we1b, HD);       // bottom half
    wsplit_kernel<<<dim3(64, 64), 256>>>(W2, w2s, KH * HD);

    // G1+GX merged: [y1 | xe] = x @ [W1 | We1_top] + [b1 | be1]
    mma_gemm<1><<<dim3(BATCH / 128, 24), 256, SMEM_DYN>>>(
        x, HD, wAs, 32, 0, 32, b1, y1, 2 * HD, be1, xe, HD);

    // LN + ReLU in place: y1 -> h
    ln_relu_2048<<<BATCH, 256>>>(y1, g1, beta1);

    // G2: hyps = h @ W2 + b2                     [8192, 8192], K=2048 (64 tiles)
    mma_gemm<0><<<dim3(BATCH / 128, KH * HD / 128), 256, SMEM_DYN>>>(
        y1, 2 * HD, w2s, 64, 0, 64, b2, out_hyps, KH * HD, nullptr, nullptr, 0);

    // G3: e[r] = hyps_perm @ We1[H:2H,:] + xe[b] [65536, 1024], K=1024
    mma_gemm<2><<<dim3(BATCH * KH / 128, HD / 128), 256, SMEM_DYN>>>(
        out_hyps, KH * HD, we1b, 32, 0, 32, xe, e, HD, nullptr, nullptr, 0);

    // scores = sigmoid(relu(LN(e)) . We2 + be2)
    score_kernel<<<BATCH * KH, 256>>>(e, ge, betae, We2, be2, out_scores);

    // argmax / gather
    finalize_kernel<<<BATCH, 256>>>(out_scores, out_hyps,
                                    out_best_hyp, out_best_idx, out_best_sc);
}

// round 16
// speedup vs baseline: 1.0756x; 1.0756x over previous
#include <cuda_runtime.h>
#include <cuda_fp16.h>
#include <math.h>
#include <stdint.h>

#define HD    1024
#define KH    8
#define BATCH 8192
#define EPSLN 1e-5f

// ---------------- scratch (static device globals; no allocs allowed) --------
static __device__ float    g_y1 [(size_t)BATCH * 2 * HD];        //  64 MB G1 out -> h in place
static __device__ float    g_xe [(size_t)BATCH * HD];            //  32 MB GX out
static __device__ float    g_e  [(size_t)BATCH * KH * HD];       // 256 MB G3 out (permuted rows)
static __device__ uint32_t g_wAs [(size_t)24 * 32 * 4096];       //  12.6 MB W1^T + We1-top tiles
static __device__ uint32_t g_w2s [(size_t)2 * HD * KH * HD];     //  64 MB W2^T split tiles
static __device__ uint32_t g_we1b[(size_t)HD * HD];              //   4 MB We1-bottom tiles

// ============================ PTX helpers (portable, sm_80+) =================
__device__ __forceinline__ uint32_t smem_u32(const void* p) {
    uint32_t a;
    asm("{ .reg .u64 t; cvta.to.shared.u64 t, %1; cvt.u32.u64 %0, t; }" : "=r"(a) : "l"(p));
    return a;
}
__device__ __forceinline__ void cp_async16(uint32_t saddr, const void* g) {
    asm volatile("cp.async.cg.shared.global [%0], [%1], 16;" :: "r"(saddr), "l"(g));
}
__device__ __forceinline__ void cp_commit() {
    asm volatile("cp.async.commit_group;" ::: "memory");
}
template<int N> __device__ __forceinline__ void cp_wait() {
    asm volatile("cp.async.wait_group %0;" :: "n"(N) : "memory");
}
// fp16 error-compensated split of a pair of fp32 values -> hi word, lo word
__device__ __forceinline__ void split2h(float v0, float v1, uint32_t& hw, uint32_t& lw) {
    __half2 h = __floats2half2_rn(v0, v1);
    float2 hf = __half22float2(h);
    __half2 l = __floats2half2_rn(v0 - hf.x, v1 - hf.y);
    hw = *(uint32_t*)&h;
    lw = *(uint32_t*)&l;
}
__device__ __forceinline__ void mma16(float* c, const uint32_t* a, const uint32_t* b) {
    asm volatile(
        "mma.sync.aligned.m16n8k16.row.col.f32.f16.f16.f32 "
        "{%0,%1,%2,%3}, {%4,%5,%6,%7}, {%8,%9}, {%0,%1,%2,%3};"
        : "+f"(c[0]), "+f"(c[1]), "+f"(c[2]), "+f"(c[3])
        : "r"(a[0]), "r"(a[1]), "r"(a[2]), "r"(a[3]), "r"(b[0]), "r"(b[1]));
}

// A fragment load from smem (additive swizzle slot = r*16 + ((p + 4r) & 15))
__device__ __forceinline__ void lds_a8(const float2* __restrict__ sAf,
                                       int wm, int g, int tg, int kb, float2 ar[2][4]) {
    #pragma unroll
    for (int mt = 0; mt < 2; mt++) {
        const int r0 = wm * 32 + mt * 16 + g;
        const int r1 = r0 + 8;
        const int p0 = kb * 8 + tg, p1 = p0 + 4;
        ar[mt][0] = sAf[r0 * 16 + ((p0 + r0 * 4) & 15)];
        ar[mt][1] = sAf[r1 * 16 + ((p0 + r1 * 4) & 15)];
        ar[mt][2] = sAf[r0 * 16 + ((p1 + r0 * 4) & 15)];
        ar[mt][3] = sAf[r1 * 16 + ((p1 + r1 * 4) & 15)];
    }
}

// ============================ fp16x3 GEMM =====================================
// C[M,N] = A @ B^T.  A: plain fp32 row-major via cp.async -> smem -> regs,
// split to fp16 hi/lo in-register. B: pre-split weight tiles (128x32k = 4096
// words). CTA 128x128, 8 warps 4x2, BK=32/stage, 3-stage ring (96 KB),
// 2 CTAs/SM, 16-wide grid swizzle. 3 MMA passes: hi*lo + lo*hi + hi*hi.
// Cross-tile A-fragment pipeline (R12/R14 structure — converged optimum; both
// deeper-pipeline variants, register-heavy R13 and LDG-based R15, regressed):
// each kb phase splits a PRE-LOADED fragment and issues the LDS for the next
// kb (next tile's kb0 comes from the already-resident next ring stage;
// cp_wait<0> before the new commit guarantees it).
// MODE 0: +bias[n].
// MODE 1: dual output: bn < N -> C (+aux), bn >= N -> C2 (+aux2), width N2.
// MODE 2: A rows permuted from hyps (r = kk*8192+b), +aux[(row&8191)*N + n].
#define SMEM_DYN (3 * 32 * 1024)

template<int MODE>
__global__ void __launch_bounds__(256, 2) mma_gemm(
    const float* __restrict__ A, int lda,
    const uint32_t* __restrict__ Bt, int nBk, int koff, int ntk,  // ntk = # 32k tiles
    const float* __restrict__ aux, float* __restrict__ C, int N,
    const float* __restrict__ aux2, float* __restrict__ C2, int N2)
{
    extern __shared__ uint32_t smu[];        // 3 stages x 8192 words (A 4096 | B 4096)
    const int tid  = threadIdx.x;
    const int lane = tid & 31, wid = tid >> 5;
    const int wm = wid & 3, wn = wid >> 2;
    const int g = lane >> 2, tg = lane & 3;
    const int sx = (g & 2) << 1;             // B-side XOR swizzle term

    // grid swizzle: waves cover ~16 m-blocks x ~N n-blocks (L2 locality)
    const int GM = gridDim.x, GN = gridDim.y;
    const int L = blockIdx.x + blockIdx.y * GM;
    const int chunk = L >> 4;
    const int nb = chunk % GN;
    const int mb = (chunk / GN) * 16 + (L & 15);
    const int bm = mb * 128, bn = nb * 128;

    float acc[2][8][4];
    #pragma unroll
    for (int mt = 0; mt < 2; mt++)
        #pragma unroll
        for (int nt = 0; nt < 8; nt++)
            #pragma unroll
            for (int i = 0; i < 4; i++) acc[mt][nt][i] = 0.f;

    // A base: MODE 2 maps GEMM row r = kk*8192 + b onto hyps[b][kk*HD + .]
    const float* Abase;
    if (MODE == 2) {
        const int kk = mb >> 6, b0 = (mb & 63) * 128;
        Abase = A + (size_t)b0 * lda + kk * HD;
    } else {
        Abase = A + (size_t)bm * lda;
    }
    const uint32_t* Bb = Bt + ((size_t)nb * nBk + koff) * 4096 + tid * 4;

    auto load_stage = [&](int t, int buf) {
        const int k0 = t * 32;
        const uint32_t dA = smem_u32(&smu[buf * 8192]);
        #pragma unroll
        for (int i = 0; i < 4; i++) {        // A: 1024 x 16B chunks
            int c = tid + i * 256;
            int row = c >> 3, cp = c & 7;
            int slot = row * 16 + (((cp << 1) + (row << 2)) & 15);
            cp_async16(dA + slot * 8, Abase + (size_t)row * lda + k0 + cp * 4);
        }
        const uint32_t dB = smem_u32(&smu[buf * 8192 + 4096 + tid * 4]);
        const uint32_t* b = Bb + (size_t)t * 4096;
        #pragma unroll
        for (int i = 0; i < 4; i++) cp_async16(dB + i * 4096, b + i * 1024);
    };

    load_stage(0, 0); cp_commit();
    if (ntk > 1) { load_stage(1, 1); cp_commit(); }
    cp_wait<0>(); __syncthreads();           // stages 0 (and 1) fully visible

    float2 ar[2][4];
    lds_a8((const float2*)&smu[0], wm, g, tg, 0, ar);   // tile 0, kb 0

    for (int it = 0; it < ntk; it++) {
        if (it) { cp_wait<0>(); __syncthreads(); }       // stages <= it+1 visible
        if (it + 2 < ntk) { load_stage(it + 2, (it + 2) % 3); cp_commit(); }

        const float2*   sAc = (const float2*)&smu[(it % 3) * 8192];
        const uint32_t* sB  = &smu[(it % 3) * 8192 + 4096];
        const float2*   sAn = (it + 1 < ntk)
                            ? (const float2*)&smu[((it + 1) % 3) * 8192] : sAc;

        #pragma unroll
        for (int kb = 0; kb < 2; kb++) {
            // split the pre-loaded fragment, then issue LDS for the next one
            uint32_t aH[2][4], aL[2][4];
            #pragma unroll
            for (int mt = 0; mt < 2; mt++)
                #pragma unroll
                for (int i = 0; i < 4; i++)
                    split2h(ar[mt][i].x, ar[mt][i].y, aH[mt][i], aL[mt][i]);
            if (kb == 0) lds_a8(sAc, wm, g, tg, 1, ar);  // this tile, kb1
            else         lds_a8(sAn, wm, g, tg, 0, ar);  // next tile, kb0

            const uint32_t* Bk = sB + kb * 2048;
            #pragma unroll
            for (int nh = 0; nh < 2; nh++) {
                uint32_t bH[4][2], bL[4][2];
                #pragma unroll
                for (int q = 0; q < 4; q++) {
                    const int n = wn * 64 + (nh * 4 + q) * 8 + g;
                    uint2 u0 = *(const uint2*)(Bk + (n * 8 + (tg ^ sx)) * 2);
                    uint2 u1 = *(const uint2*)(Bk + (n * 8 + ((tg + 4) ^ sx)) * 2);
                    bH[q][0] = u0.x; bH[q][1] = u1.x;
                    bL[q][0] = u0.y; bL[q][1] = u1.y;
                }
                float* a0 = &acc[0][nh * 4][0];
                float* a1 = &acc[1][nh * 4][0];
                #pragma unroll
                for (int q = 0; q < 4; q++) { mma16(a0 + q * 4, aH[0], bL[q]); mma16(a1 + q * 4, aH[1], bL[q]); }
                #pragma unroll
                for (int q = 0; q < 4; q++) { mma16(a0 + q * 4, aL[0], bH[q]); mma16(a1 + q * 4, aL[1], bH[q]); }
                #pragma unroll
                for (int q = 0; q < 4; q++) { mma16(a0 + q * 4, aH[0], bH[q]); mma16(a1 + q * 4, aH[1], bH[q]); }
            }
        }
    }

    // ---------------- epilogue --------------------------------------------
    float* Cp = C;
    const float* ax = aux;
    int Nn = N, cb = bn;
    if (MODE == 1 && bn >= N) { Cp = C2; ax = aux2; Nn = N2; cb = bn - N; }

    #pragma unroll
    for (int mt = 0; mt < 2; mt++) {
        const int row0 = bm + wm * 32 + mt * 16 + g;
        #pragma unroll
        for (int nt = 0; nt < 8; nt++) {
            const int col = cb + wn * 64 + nt * 8 + 2 * tg;
            float o0 = acc[mt][nt][0], o1 = acc[mt][nt][1];
            float o2 = acc[mt][nt][2], o3 = acc[mt][nt][3];
            if (MODE != 2) {
                float z0 = ax[col], z1 = ax[col + 1];
                o0 += z0; o1 += z1; o2 += z0; o3 += z1;
            } else {
                const float* a0 = aux + (size_t)(row0 & (BATCH - 1)) * Nn + col;
                const float* a1 = aux + (size_t)((row0 + 8) & (BATCH - 1)) * Nn + col;
                o0 += a0[0]; o1 += a0[1]; o2 += a1[0]; o3 += a1[1];
            }
            *(float2*)(Cp + (size_t)row0 * Nn + col)       = make_float2(o0, o1);
            *(float2*)(Cp + (size_t)(row0 + 8) * Nn + col) = make_float2(o2, o3);
        }
    }
}

// ================= one-time weight transpose+split+tile (merged) =============
// One launch covers all four weight regions via blockIdx.z dispatch:
//   z=0: W1      [1024 x 2048] -> wAs  (16 nblk x 32 ktile)
//   z=1: We1 top [1024 x 1024] -> wAs + 16*32*4096 (8 nblk x 32 ktile)
//   z=2: We1 bot [1024 x 1024] -> we1b (8 nblk x 32 ktile)
//   z=3: W2      [2048 x 8192] -> w2s  (64 nblk x 64 ktile)
// Grid: (64, 64, 4); blocks outside a region's extent exit early.
// Tile format: word pair for (n-row, k even):
//   idx = kb*2048 + (n*8 + k2s)*2, k2s = ((k>>1)&7) ^ ((n&2)<<1);
//   [idx] = {hi(k),hi(k+1)}, [idx+1] = {lo(k),lo(k+1)}.
__global__ void __launch_bounds__(256) wsplit_all_kernel(
    const float* __restrict__ W1, const float* __restrict__ We1,
    const float* __restrict__ W2,
    uint32_t* __restrict__ wAs, uint32_t* __restrict__ we1b,
    uint32_t* __restrict__ w2s)
{
    const float* W; uint32_t* out;
    int N, nblk, kblk;
    switch (blockIdx.z) {
        case 0: W = W1;                        out = wAs;                   N = 2 * HD;  nblk = 16; kblk = 32; break;
        case 1: W = We1;                       out = wAs + (size_t)16 * 32 * 4096; N = HD; nblk = 8; kblk = 32; break;
        case 2: W = We1 + (size_t)HD * HD;     out = we1b;                  N = HD;      nblk = 8;  kblk = 32; break;
        default: W = W2;                       out = w2s;                   N = KH * HD; nblk = 64; kblk = 64; break;
    }
    if ((int)blockIdx.x >= nblk || (int)blockIdx.y >= kblk) return;

    __shared__ float s[32 * 132];
    const int t = threadIdx.x;
    #pragma unroll
    for (int i = 0; i < 16; i++) {
        int e = t + i * 256;
        int kl = e >> 7, nl = e & 127;
        s[kl * 132 + nl] = W[(size_t)(blockIdx.y * 32 + kl) * N + blockIdx.x * 128 + nl];
    }
    __syncthreads();
    uint32_t* ob = out + ((size_t)blockIdx.x * kblk + blockIdx.y) * 4096;
    #pragma unroll
    for (int i = 0; i < 16; i++) {
        int o = t + i * 256;                 // word index in tile
        int w = o & 1, q = o >> 1;           // q = kb*1024 + nl*8 + k2s
        int kb = q >> 10, r = q & 1023;
        int nl = r >> 3, k2s = r & 7;
        int k2 = k2s ^ ((nl & 2) << 1);
        int k = kb * 16 + k2 * 2;
        uint32_t hw, lw;
        split2h(s[k * 132 + nl], s[(k + 1) * 132 + nl], hw, lw);
        ob[o] = w ? lw : hw;
    }
}

// ---------------- block reduction of two scalars (256 threads) --------------
__device__ __forceinline__ void block_reduce2(float& a, float& b) {
    __shared__ float sa[8], sb[8];
    float x = a, y = b;
    #pragma unroll
    for (int o = 16; o > 0; o >>= 1) {
        x += __shfl_down_sync(0xffffffffu, x, o);
        y += __shfl_down_sync(0xffffffffu, y, o);
    }
    int w = threadIdx.x >> 5;
    if ((threadIdx.x & 31) == 0) { sa[w] = x; sb[w] = y; }
    __syncthreads();
    if (threadIdx.x == 0) {
        float xs = 0.f, ys = 0.f;
        #pragma unroll
        for (int i = 0; i < 8; i++) { xs += sa[i]; ys += sb[i]; }
        sa[0] = xs; sb[0] = ys;
    }
    __syncthreads();
    a = sa[0]; b = sb[0];
    __syncthreads();
}

// -------- LN + ReLU over width 2048, in place (h overwrites y1) -------------
__global__ void __launch_bounds__(256) ln_relu_2048(
    float* __restrict__ y, const float* __restrict__ g, const float* __restrict__ beta)
{
    const int row = blockIdx.x;
    float* p = y + (size_t)row * 2048;
    const int j0 = threadIdx.x * 8;
    float v[8];
    *(float4*)&v[0] = *(const float4*)(p + j0);
    *(float4*)&v[4] = *(const float4*)(p + j0 + 4);
    float s = 0.f, ss = 0.f;
    #pragma unroll
    for (int i = 0; i < 8; i++) { s += v[i]; ss += v[i] * v[i]; }
    block_reduce2(s, ss);
    const float mean = s * (1.f / 2048.f);
    const float var  = ss * (1.f / 2048.f) - mean * mean;
    const float rs   = rsqrtf(var + EPSLN);
    float o[8];
    #pragma unroll
    for (int i = 0; i < 8; i++) {
        int j = j0 + i;
        o[i] = fmaxf((v[i] - mean) * rs * g[j] + beta[j], 0.f);
    }
    *(float4*)(p + j0)     = *(float4*)&o[0];
    *(float4*)(p + j0 + 4) = *(float4*)&o[4];
}

// ---------------- per permuted row: LN + ReLU + dot(We2) + sigmoid ----------
// float4 loads, same per-thread element order as before (j = t + i*256 maps to
// j0 = t*4 + i lanes re-ordered BLOCK-wise but each thread's private sum uses
// its own 4 elements; to keep the fp32 summation order IDENTICAL to R14 we
// keep the strided mapping: thread t sums e[t], e[t+256], e[t+512], e[t+768].
// float4 would change per-thread element sets, so we retain scalar loads for
// v[] (coalesced 32-bit) — bit-exact reduction preserved.
__global__ void __launch_bounds__(256) score_kernel(
    const float* __restrict__ e, const float* __restrict__ ge,
    const float* __restrict__ betae, const float* __restrict__ We2,
    const float* __restrict__ be2, float* __restrict__ scores)
{
    const int r = blockIdx.x;               // r = k*8192 + b
    const float* p = e + (size_t)r * HD;
    const int t = threadIdx.x;
    float v[4];
    float s = 0.f, ss = 0.f;
    #pragma unroll
    for (int i = 0; i < 4; i++) {
        v[i] = p[t + i * 256];
        s += v[i]; ss += v[i] * v[i];
    }
    block_reduce2(s, ss);
    const float mean = s * (1.f / 1024.f);
    const float var  = ss * (1.f / 1024.f) - mean * mean;
    const float rs   = rsqrtf(var + EPSLN);
    float d = 0.f, dummy = 0.f;
    #pragma unroll
    for (int i = 0; i < 4; i++) {
        int j = t + i * 256;
        float o = fmaxf((v[i] - mean) * rs * ge[j] + betae[j], 0.f);
        d = fmaf(o, We2[j], d);
    }
    block_reduce2(d, dummy);
    if (t == 0) {
        int b = r & (BATCH - 1), k = r >> 13;
        scores[(size_t)b * KH + k] = 1.f / (1.f + expf(-(d + be2[0])));
    }
}

// ---------------- argmax over K, gather best hypothesis ---------------------
__global__ void __launch_bounds__(256) finalize_kernel(
    const float* __restrict__ scores, const float* __restrict__ hyps,
    float* __restrict__ best_hyp, float* __restrict__ best_idx,
    float* __restrict__ best_sc)
{
    const int b = blockIdx.x;
    __shared__ int sidx;
    if (threadIdx.x == 0) {
        const float* sc = scores + (size_t)b * KH;
        int bi = 0; float bv = sc[0];
        #pragma unroll
        for (int k = 1; k < KH; k++)
            if (sc[k] > bv) { bv = sc[k]; bi = k; }
        sidx = bi;
        best_idx[b] = (float)bi;
        best_sc[b]  = bv;
    }
    __syncthreads();
    // bit-exact float4 gather copy (rows are 4 KB aligned)
    const float4* src = (const float4*)(hyps + ((size_t)b * KH + sidx) * HD);
    float4* dst = (float4*)(best_hyp + (size_t)b * HD);
    dst[threadIdx.x] = src[threadIdx.x];     // 256 threads x 16 B = 4 KB row
}

// ---------------- launcher ---------------------------------------------------
extern "C" void kernel_launch(void* const* d_in, const int* in_sizes, int n_in,
                              void* d_out, int out_size)
{
    const float* x     = (const float*)d_in[0];
    const float* W1    = (const float*)d_in[1];
    const float* b1    = (const float*)d_in[2];
    const float* g1    = (const float*)d_in[3];
    const float* beta1 = (const float*)d_in[4];
    const float* W2    = (const float*)d_in[5];
    const float* b2    = (const float*)d_in[6];
    const float* We1   = (const float*)d_in[7];
    const float* be1   = (const float*)d_in[8];
    const float* ge    = (const float*)d_in[9];
    const float* betae = (const float*)d_in[10];
    const float* We2   = (const float*)d_in[11];
    const float* be2   = (const float*)d_in[12];

    float* out = (float*)d_out;
    float* out_best_hyp = out;                                    // [B, H]
    float* out_hyps     = out + (size_t)BATCH * HD;               // [B, K, H]
    float* out_scores   = out_hyps + (size_t)BATCH * KH * HD;     // [B, K]
    float* out_best_idx = out_scores + (size_t)BATCH * KH;        // [B, 1]
    float* out_best_sc  = out_best_idx + BATCH;                   // [B, 1]

    float *y1, *xe, *e;
    uint32_t *wAs, *w2s, *we1b;
    cudaGetSymbolAddress((void**)&y1,   g_y1);
    cudaGetSymbolAddress((void**)&xe,   g_xe);
    cudaGetSymbolAddress((void**)&e,    g_e);
    cudaGetSymbolAddress((void**)&wAs,  g_wAs);
    cudaGetSymbolAddress((void**)&w2s,  g_w2s);
    cudaGetSymbolAddress((void**)&we1b, g_we1b);

    cudaFuncSetAttribute(mma_gemm<0>, cudaFuncAttributeMaxDynamicSharedMemorySize, SMEM_DYN);
    cudaFuncSetAttribute(mma_gemm<1>, cudaFuncAttributeMaxDynamicSharedMemorySize, SMEM_DYN);
    cudaFuncSetAttribute(mma_gemm<2>, cudaFuncAttributeMaxDynamicSharedMemorySize, SMEM_DYN);

    // weight split tiles: single merged launch (z-dispatch over 4 regions)
    wsplit_all_kernel<<<dim3(64, 64, 4), 256>>>(W1, We1, W2, wAs, we1b, w2s);

    // G1+GX merged: [y1 | xe] = x @ [W1 | We1_top] + [b1 | be1]
    mma_gemm<1><<<dim3(BATCH / 128, 24), 256, SMEM_DYN>>>(
        x, HD, wAs, 32, 0, 32, b1, y1, 2 * HD, be1, xe, HD);

    // LN + ReLU in place: y1 -> h
    ln_relu_2048<<<BATCH, 256>>>(y1, g1, beta1);

    // G2: hyps = h @ W2 + b2                     [8192, 8192], K=2048 (64 tiles)
    mma_gemm<0><<<dim3(BATCH / 128, KH * HD / 128), 256, SMEM_DYN>>>(
        y1, 2 * HD, w2s, 64, 0, 64, b2, out_hyps, KH * HD, nullptr, nullptr, 0);

    // G3: e[r] = hyps_perm @ We1[H:2H,:] + xe[b] [65536, 1024], K=1024
    mma_gemm<2><<<dim3(BATCH * KH / 128, HD / 128), 256, SMEM_DYN>>>(
        out_hyps, KH * HD, we1b, 32, 0, 32, xe, e, HD, nullptr, nullptr, 0);

    // scores = sigmoid(relu(LN(e)) . We2 + be2)
    score_kernel<<<BATCH * KH, 256>>>(e, ge, betae, We2, be2, out_scores);

    // argmax / gather
    finalize_kernel<<<BATCH, 256>>>(out_scores, out_hyps,
                                    out_best_hyp, out_best_idx, out_best_sc);
}

// round 17
// speedup vs baseline: 1.0909x; 1.0142x over previous
#include <cuda_runtime.h>
#include <cuda_fp16.h>
#include <math.h>
#include <stdint.h>

#define HD    1024
#define KH    8
#define BATCH 8192
#define EPSLN 1e-5f

// ---------------- scratch (static device globals; no allocs allowed) --------
static __device__ float    g_y1 [(size_t)BATCH * 2 * HD];        //  64 MB G1 out -> h in place
static __device__ float    g_xe [(size_t)BATCH * HD];            //  32 MB GX out
static __device__ float    g_e  [(size_t)BATCH * KH * HD];       // 256 MB G3 out (permuted rows)
static __device__ uint32_t g_wAs [(size_t)24 * 32 * 4096];       //  12.6 MB W1^T + We1-top tiles
static __device__ uint32_t g_w2s [(size_t)2 * HD * KH * HD];     //  64 MB W2^T split tiles
static __device__ uint32_t g_we1b[(size_t)HD * HD];              //   4 MB We1-bottom tiles

// ============================ PTX helpers (portable, sm_80+) =================
__device__ __forceinline__ uint32_t smem_u32(const void* p) {
    uint32_t a;
    asm("{ .reg .u64 t; cvta.to.shared.u64 t, %1; cvt.u32.u64 %0, t; }" : "=r"(a) : "l"(p));
    return a;
}
__device__ __forceinline__ void cp_async16(uint32_t saddr, const void* g) {
    asm volatile("cp.async.cg.shared.global [%0], [%1], 16;" :: "r"(saddr), "l"(g));
}
__device__ __forceinline__ void cp_commit() {
    asm volatile("cp.async.commit_group;" ::: "memory");
}
template<int N> __device__ __forceinline__ void cp_wait() {
    asm volatile("cp.async.wait_group %0;" :: "n"(N) : "memory");
}
// fp16 error-compensated split of a pair of fp32 values -> hi word, lo word
__device__ __forceinline__ void split2h(float v0, float v1, uint32_t& hw, uint32_t& lw) {
    __half2 h = __floats2half2_rn(v0, v1);
    float2 hf = __half22float2(h);
    __half2 l = __floats2half2_rn(v0 - hf.x, v1 - hf.y);
    hw = *(uint32_t*)&h;
    lw = *(uint32_t*)&l;
}
__device__ __forceinline__ void mma16(float* c, const uint32_t* a, const uint32_t* b) {
    asm volatile(
        "mma.sync.aligned.m16n8k16.row.col.f32.f16.f16.f32 "
        "{%0,%1,%2,%3}, {%4,%5,%6,%7}, {%8,%9}, {%0,%1,%2,%3};"
        : "+f"(c[0]), "+f"(c[1]), "+f"(c[2]), "+f"(c[3])
        : "r"(a[0]), "r"(a[1]), "r"(a[2]), "r"(a[3]), "r"(b[0]), "r"(b[1]));
}

// A fragment load from smem (additive swizzle slot = r*16 + ((p + 4r) & 15))
__device__ __forceinline__ void lds_a8(const float2* __restrict__ sAf,
                                       int wm, int g, int tg, int kb, float2 ar[2][4]) {
    #pragma unroll
    for (int mt = 0; mt < 2; mt++) {
        const int r0 = wm * 32 + mt * 16 + g;
        const int r1 = r0 + 8;
        const int p0 = kb * 8 + tg, p1 = p0 + 4;
        ar[mt][0] = sAf[r0 * 16 + ((p0 + r0 * 4) & 15)];
        ar[mt][1] = sAf[r1 * 16 + ((p0 + r1 * 4) & 15)];
        ar[mt][2] = sAf[r0 * 16 + ((p1 + r0 * 4) & 15)];
        ar[mt][3] = sAf[r1 * 16 + ((p1 + r1 * 4) & 15)];
    }
}

// ============================ fp16x3 GEMM =====================================
// C[M,N] = A @ B^T.  A: plain fp32 row-major via cp.async -> smem -> regs,
// split to fp16 hi/lo in-register. B: pre-split weight tiles (128x32k = 4096
// words). CTA 128x128, 8 warps 4x2, BK=32/stage, 3-stage ring (96 KB),
// 2 CTAs/SM, 16-wide grid swizzle. 3 MMA passes: hi*lo + lo*hi + hi*hi.
// Cross-tile A-fragment pipeline (R12/R14 structure — converged optimum).
// MODE 0: +bias[n].
// MODE 1: dual output: bn < N -> C (+aux), bn >= N -> C2 (+aux2), width N2.
// MODE 2: A rows permuted from hyps (r = kk*8192+b), +aux[(row&8191)*N + n].
#define SMEM_DYN (3 * 32 * 1024)

template<int MODE>
__global__ void __launch_bounds__(256, 2) mma_gemm(
    const float* __restrict__ A, int lda,
    const uint32_t* __restrict__ Bt, int nBk, int koff, int ntk,  // ntk = # 32k tiles
    const float* __restrict__ aux, float* __restrict__ C, int N,
    const float* __restrict__ aux2, float* __restrict__ C2, int N2)
{
    extern __shared__ uint32_t smu[];        // 3 stages x 8192 words (A 4096 | B 4096)
    const int tid  = threadIdx.x;
    const int lane = tid & 31, wid = tid >> 5;
    const int wm = wid & 3, wn = wid >> 2;
    const int g = lane >> 2, tg = lane & 3;
    const int sx = (g & 2) << 1;             // B-side XOR swizzle term

    // grid swizzle: waves cover ~16 m-blocks x ~N n-blocks (L2 locality)
    const int GM = gridDim.x, GN = gridDim.y;
    const int L = blockIdx.x + blockIdx.y * GM;
    const int chunk = L >> 4;
    const int nb = chunk % GN;
    const int mb = (chunk / GN) * 16 + (L & 15);
    const int bm = mb * 128, bn = nb * 128;

    float acc[2][8][4];
    #pragma unroll
    for (int mt = 0; mt < 2; mt++)
        #pragma unroll
        for (int nt = 0; nt < 8; nt++)
            #pragma unroll
            for (int i = 0; i < 4; i++) acc[mt][nt][i] = 0.f;

    // A base: MODE 2 maps GEMM row r = kk*8192 + b onto hyps[b][kk*HD + .]
    const float* Abase;
    if (MODE == 2) {
        const int kk = mb >> 6, b0 = (mb & 63) * 128;
        Abase = A + (size_t)b0 * lda + kk * HD;
    } else {
        Abase = A + (size_t)bm * lda;
    }
    const uint32_t* Bb = Bt + ((size_t)nb * nBk + koff) * 4096 + tid * 4;

    auto load_stage = [&](int t, int buf) {
        const int k0 = t * 32;
        const uint32_t dA = smem_u32(&smu[buf * 8192]);
        #pragma unroll
        for (int i = 0; i < 4; i++) {        // A: 1024 x 16B chunks
            int c = tid + i * 256;
            int row = c >> 3, cp = c & 7;
            int slot = row * 16 + (((cp << 1) + (row << 2)) & 15);
            cp_async16(dA + slot * 8, Abase + (size_t)row * lda + k0 + cp * 4);
        }
        const uint32_t dB = smem_u32(&smu[buf * 8192 + 4096 + tid * 4]);
        const uint32_t* b = Bb + (size_t)t * 4096;
        #pragma unroll
        for (int i = 0; i < 4; i++) cp_async16(dB + i * 4096, b + i * 1024);
    };

    load_stage(0, 0); cp_commit();
    if (ntk > 1) { load_stage(1, 1); cp_commit(); }
    cp_wait<0>(); __syncthreads();           // stages 0 (and 1) fully visible

    float2 ar[2][4];
    lds_a8((const float2*)&smu[0], wm, g, tg, 0, ar);   // tile 0, kb 0

    for (int it = 0; it < ntk; it++) {
        if (it) { cp_wait<0>(); __syncthreads(); }       // stages <= it+1 visible
        if (it + 2 < ntk) { load_stage(it + 2, (it + 2) % 3); cp_commit(); }

        const float2*   sAc = (const float2*)&smu[(it % 3) * 8192];
        const uint32_t* sB  = &smu[(it % 3) * 8192 + 4096];
        const float2*   sAn = (it + 1 < ntk)
                            ? (const float2*)&smu[((it + 1) % 3) * 8192] : sAc;

        #pragma unroll
        for (int kb = 0; kb < 2; kb++) {
            // split the pre-loaded fragment, then issue LDS for the next one
            uint32_t aH[2][4], aL[2][4];
            #pragma unroll
            for (int mt = 0; mt < 2; mt++)
                #pragma unroll
                for (int i = 0; i < 4; i++)
                    split2h(ar[mt][i].x, ar[mt][i].y, aH[mt][i], aL[mt][i]);
            if (kb == 0) lds_a8(sAc, wm, g, tg, 1, ar);  // this tile, kb1
            else         lds_a8(sAn, wm, g, tg, 0, ar);  // next tile, kb0

            const uint32_t* Bk = sB + kb * 2048;
            #pragma unroll
            for (int nh = 0; nh < 2; nh++) {
                uint32_t bH[4][2], bL[4][2];
                #pragma unroll
                for (int q = 0; q < 4; q++) {
                    const int n = wn * 64 + (nh * 4 + q) * 8 + g;
                    uint2 u0 = *(const uint2*)(Bk + (n * 8 + (tg ^ sx)) * 2);
                    uint2 u1 = *(const uint2*)(Bk + (n * 8 + ((tg + 4) ^ sx)) * 2);
                    bH[q][0] = u0.x; bH[q][1] = u1.x;
                    bL[q][0] = u0.y; bL[q][1] = u1.y;
                }
                float* a0 = &acc[0][nh * 4][0];
                float* a1 = &acc[1][nh * 4][0];
                #pragma unroll
                for (int q = 0; q < 4; q++) { mma16(a0 + q * 4, aH[0], bL[q]); mma16(a1 + q * 4, aH[1], bL[q]); }
                #pragma unroll
                for (int q = 0; q < 4; q++) { mma16(a0 + q * 4, aL[0], bH[q]); mma16(a1 + q * 4, aL[1], bH[q]); }
                #pragma unroll
                for (int q = 0; q < 4; q++) { mma16(a0 + q * 4, aH[0], bH[q]); mma16(a1 + q * 4, aH[1], bH[q]); }
            }
        }
    }

    // ---------------- epilogue --------------------------------------------
    float* Cp = C;
    const float* ax = aux;
    int Nn = N, cb = bn;
    if (MODE == 1 && bn >= N) { Cp = C2; ax = aux2; Nn = N2; cb = bn - N; }

    #pragma unroll
    for (int mt = 0; mt < 2; mt++) {
        const int row0 = bm + wm * 32 + mt * 16 + g;
        #pragma unroll
        for (int nt = 0; nt < 8; nt++) {
            const int col = cb + wn * 64 + nt * 8 + 2 * tg;
            float o0 = acc[mt][nt][0], o1 = acc[mt][nt][1];
            float o2 = acc[mt][nt][2], o3 = acc[mt][nt][3];
            if (MODE != 2) {
                float z0 = ax[col], z1 = ax[col + 1];
                o0 += z0; o1 += z1; o2 += z0; o3 += z1;
            } else {
                const float* a0 = aux + (size_t)(row0 & (BATCH - 1)) * Nn + col;
                const float* a1 = aux + (size_t)((row0 + 8) & (BATCH - 1)) * Nn + col;
                o0 += a0[0]; o1 += a0[1]; o2 += a1[0]; o3 += a1[1];
            }
            *(float2*)(Cp + (size_t)row0 * Nn + col)       = make_float2(o0, o1);
            *(float2*)(Cp + (size_t)(row0 + 8) * Nn + col) = make_float2(o2, o3);
        }
    }
}

// ================= one-time weight transpose+split+tile (merged) =============
// One launch covers all four weight regions via blockIdx.z dispatch:
//   z=0: W1      [1024 x 2048] -> wAs  (16 nblk x 32 ktile)
//   z=1: We1 top [1024 x 1024] -> wAs + 16*32*4096 (8 nblk x 32 ktile)
//   z=2: We1 bot [1024 x 1024] -> we1b (8 nblk x 32 ktile)
//   z=3: W2      [2048 x 8192] -> w2s  (64 nblk x 64 ktile)
__global__ void __launch_bounds__(256) wsplit_all_kernel(
    const float* __restrict__ W1, const float* __restrict__ We1,
    const float* __restrict__ W2,
    uint32_t* __restrict__ wAs, uint32_t* __restrict__ we1b,
    uint32_t* __restrict__ w2s)
{
    const float* W; uint32_t* out;
    int N, nblk, kblk;
    switch (blockIdx.z) {
        case 0: W = W1;                        out = wAs;                   N = 2 * HD;  nblk = 16; kblk = 32; break;
        case 1: W = We1;                       out = wAs + (size_t)16 * 32 * 4096; N = HD; nblk = 8; kblk = 32; break;
        case 2: W = We1 + (size_t)HD * HD;     out = we1b;                  N = HD;      nblk = 8;  kblk = 32; break;
        default: W = W2;                       out = w2s;                   N = KH * HD; nblk = 64; kblk = 64; break;
    }
    if ((int)blockIdx.x >= nblk || (int)blockIdx.y >= kblk) return;

    __shared__ float s[32 * 132];
    const int t = threadIdx.x;
    #pragma unroll
    for (int i = 0; i < 16; i++) {
        int e = t + i * 256;
        int kl = e >> 7, nl = e & 127;
        s[kl * 132 + nl] = W[(size_t)(blockIdx.y * 32 + kl) * N + blockIdx.x * 128 + nl];
    }
    __syncthreads();
    uint32_t* ob = out + ((size_t)blockIdx.x * kblk + blockIdx.y) * 4096;
    #pragma unroll
    for (int i = 0; i < 16; i++) {
        int o = t + i * 256;                 // word index in tile
        int w = o & 1, q = o >> 1;           // q = kb*1024 + nl*8 + k2s
        int kb = q >> 10, r = q & 1023;
        int nl = r >> 3, k2s = r & 7;
        int k2 = k2s ^ ((nl & 2) << 1);
        int k = kb * 16 + k2 * 2;
        uint32_t hw, lw;
        split2h(s[k * 132 + nl], s[(k + 1) * 132 + nl], hw, lw);
        ob[o] = w ? lw : hw;
    }
}

// ---------------- block reduction of two scalars (256 threads) --------------
__device__ __forceinline__ void block_reduce2(float& a, float& b) {
    __shared__ float sa[8], sb[8];
    float x = a, y = b;
    #pragma unroll
    for (int o = 16; o > 0; o >>= 1) {
        x += __shfl_down_sync(0xffffffffu, x, o);
        y += __shfl_down_sync(0xffffffffu, y, o);
    }
    int w = threadIdx.x >> 5;
    if ((threadIdx.x & 31) == 0) { sa[w] = x; sb[w] = y; }
    __syncthreads();
    if (threadIdx.x == 0) {
        float xs = 0.f, ys = 0.f;
        #pragma unroll
        for (int i = 0; i < 8; i++) { xs += sa[i]; ys += sb[i]; }
        sa[0] = xs; sb[0] = ys;
    }
    __syncthreads();
    a = sa[0]; b = sb[0];
    __syncthreads();
}

// -------- LN + ReLU over width 2048, in place (h overwrites y1) -------------
__global__ void __launch_bounds__(256) ln_relu_2048(
    float* __restrict__ y, const float* __restrict__ g, const float* __restrict__ beta)
{
    const int row = blockIdx.x;
    float* p = y + (size_t)row * 2048;
    const int j0 = threadIdx.x * 8;
    float v[8];
    *(float4*)&v[0] = *(const float4*)(p + j0);
    *(float4*)&v[4] = *(const float4*)(p + j0 + 4);
    float s = 0.f, ss = 0.f;
    #pragma unroll
    for (int i = 0; i < 8; i++) { s += v[i]; ss += v[i] * v[i]; }
    block_reduce2(s, ss);
    const float mean = s * (1.f / 2048.f);
    const float var  = ss * (1.f / 2048.f) - mean * mean;
    const float rs   = rsqrtf(var + EPSLN);
    float o[8];
    #pragma unroll
    for (int i = 0; i < 8; i++) {
        int j = j0 + i;
        o[i] = fmaxf((v[i] - mean) * rs * g[j] + beta[j], 0.f);
    }
    *(float4*)(p + j0)     = *(float4*)&o[0];
    *(float4*)(p + j0 + 4) = *(float4*)&o[4];
}

// ---------------- warp-per-row: LN + ReLU + dot(We2) + sigmoid --------------
// One warp handles one permuted row r = k*8192 + b (8 rows per block).
// float4 loads, shfl-only reductions, no block barriers / smem.
__global__ void __launch_bounds__(256) score_kernel(
    const float* __restrict__ e, const float* __restrict__ ge,
    const float* __restrict__ betae, const float* __restrict__ We2,
    const float* __restrict__ be2, float* __restrict__ scores)
{
    const int r = blockIdx.x * 8 + (threadIdx.x >> 5);   // row 0 .. B*K-1
    const int lane = threadIdx.x & 31;
    const float4* p = (const float4*)(e + (size_t)r * HD);

    float4 v[8];
    float s = 0.f, ss = 0.f;
    #pragma unroll
    for (int i = 0; i < 8; i++) {
        v[i] = p[lane + i * 32];             // 256 float4 = 1024 floats
        s  += v[i].x + v[i].y + v[i].z + v[i].w;
        ss += v[i].x * v[i].x + v[i].y * v[i].y + v[i].z * v[i].z + v[i].w * v[i].w;
    }
    #pragma unroll
    for (int o = 16; o > 0; o >>= 1) {
        s  += __shfl_down_sync(0xffffffffu, s,  o);
        ss += __shfl_down_sync(0xffffffffu, ss, o);
    }
    s  = __shfl_sync(0xffffffffu, s,  0);
    ss = __shfl_sync(0xffffffffu, ss, 0);

    const float mean = s * (1.f / 1024.f);
    const float var  = ss * (1.f / 1024.f) - mean * mean;
    const float rs   = rsqrtf(var + EPSLN);

    float d = 0.f;
    #pragma unroll
    for (int i = 0; i < 8; i++) {
        const int j4 = lane + i * 32;        // float4 index
        float4 gg = ((const float4*)ge)[j4];
        float4 bb = ((const float4*)betae)[j4];
        float4 ww = ((const float4*)We2)[j4];
        d = fmaf(fmaxf((v[i].x - mean) * rs * gg.x + bb.x, 0.f), ww.x, d);
        d = fmaf(fmaxf((v[i].y - mean) * rs * gg.y + bb.y, 0.f), ww.y, d);
        d = fmaf(fmaxf((v[i].z - mean) * rs * gg.z + bb.z, 0.f), ww.z, d);
        d = fmaf(fmaxf((v[i].w - mean) * rs * gg.w + bb.w, 0.f), ww.w, d);
    }
    #pragma unroll
    for (int o = 16; o > 0; o >>= 1)
        d += __shfl_down_sync(0xffffffffu, d, o);

    if (lane == 0) {
        int b = r & (BATCH - 1), k = r >> 13;
        scores[(size_t)b * KH + k] = 1.f / (1.f + expf(-(d + be2[0])));
    }
}

// ---------------- argmax over K, gather best hypothesis ---------------------
__global__ void __launch_bounds__(256) finalize_kernel(
    const float* __restrict__ scores, const float* __restrict__ hyps,
    float* __restrict__ best_hyp, float* __restrict__ best_idx,
    float* __restrict__ best_sc)
{
    const int b = blockIdx.x;
    __shared__ int sidx;
    if (threadIdx.x == 0) {
        const float* sc = scores + (size_t)b * KH;
        int bi = 0; float bv = sc[0];
        #pragma unroll
        for (int k = 1; k < KH; k++)
            if (sc[k] > bv) { bv = sc[k]; bi = k; }
        sidx = bi;
        best_idx[b] = (float)bi;
        best_sc[b]  = bv;
    }
    __syncthreads();
    // bit-exact float4 gather copy (rows are 4 KB aligned)
    const float4* src = (const float4*)(hyps + ((size_t)b * KH + sidx) * HD);
    float4* dst = (float4*)(best_hyp + (size_t)b * HD);
    dst[threadIdx.x] = src[threadIdx.x];     // 256 threads x 16 B = 4 KB row
}

// ---------------- launcher ---------------------------------------------------
extern "C" void kernel_launch(void* const* d_in, const int* in_sizes, int n_in,
                              void* d_out, int out_size)
{
    const float* x     = (const float*)d_in[0];
    const float* W1    = (const float*)d_in[1];
    const float* b1    = (const float*)d_in[2];
    const float* g1    = (const float*)d_in[3];
    const float* beta1 = (const float*)d_in[4];
    const float* W2    = (const float*)d_in[5];
    const float* b2    = (const float*)d_in[6];
    const float* We1   = (const float*)d_in[7];
    const float* be1   = (const float*)d_in[8];
    const float* ge    = (const float*)d_in[9];
    const float* betae = (const float*)d_in[10];
    const float* We2   = (const float*)d_in[11];
    const float* be2   = (const float*)d_in[12];

    float* out = (float*)d_out;
    float* out_best_hyp = out;                                    // [B, H]
    float* out_hyps     = out + (size_t)BATCH * HD;               // [B, K, H]
    float* out_scores   = out_hyps + (size_t)BATCH * KH * HD;     // [B, K]
    float* out_best_idx = out_scores + (size_t)BATCH * KH;        // [B, 1]
    float* out_best_sc  = out_best_idx + BATCH;                   // [B, 1]

    float *y1, *xe, *e;
    uint32_t *wAs, *w2s, *we1b;
    cudaGetSymbolAddress((void**)&y1,   g_y1);
    cudaGetSymbolAddress((void**)&xe,   g_xe);
    cudaGetSymbolAddress((void**)&e,    g_e);
    cudaGetSymbolAddress((void**)&wAs,  g_wAs);
    cudaGetSymbolAddress((void**)&w2s,  g_w2s);
    cudaGetSymbolAddress((void**)&we1b, g_we1b);

    cudaFuncSetAttribute(mma_gemm<0>, cudaFuncAttributeMaxDynamicSharedMemorySize, SMEM_DYN);
    cudaFuncSetAttribute(mma_gemm<1>, cudaFuncAttributeMaxDynamicSharedMemorySize, SMEM_DYN);
    cudaFuncSetAttribute(mma_gemm<2>, cudaFuncAttributeMaxDynamicSharedMemorySize, SMEM_DYN);

    // weight split tiles: single merged launch (z-dispatch over 4 regions)
    wsplit_all_kernel<<<dim3(64, 64, 4), 256>>>(W1, We1, W2, wAs, we1b, w2s);

    // G1+GX merged: [y1 | xe] = x @ [W1 | We1_top] + [b1 | be1]
    mma_gemm<1><<<dim3(BATCH / 128, 24), 256, SMEM_DYN>>>(
        x, HD, wAs, 32, 0, 32, b1, y1, 2 * HD, be1, xe, HD);

    // LN + ReLU in place: y1 -> h
    ln_relu_2048<<<BATCH, 256>>>(y1, g1, beta1);

    // G2: hyps = h @ W2 + b2                     [8192, 8192], K=2048 (64 tiles)
    mma_gemm<0><<<dim3(BATCH / 128, KH * HD / 128), 256, SMEM_DYN>>>(
        y1, 2 * HD, w2s, 64, 0, 64, b2, out_hyps, KH * HD, nullptr, nullptr, 0);

    // G3: e[r] = hyps_perm @ We1[H:2H,:] + xe[b] [65536, 1024], K=1024
    mma_gemm<2><<<dim3(BATCH * KH / 128, HD / 128), 256, SMEM_DYN>>>(
        out_hyps, KH * HD, we1b, 32, 0, 32, xe, e, HD, nullptr, nullptr, 0);

    // scores = sigmoid(relu(LN(e)) . We2 + be2)   — warp-per-row
    score_kernel<<<BATCH * KH / 8, 256>>>(e, ge, betae, We2, be2, out_scores);

    // argmax / gather
    finalize_kernel<<<BATCH, 256>>>(out_scores, out_hyps,
                                    out_best_hyp, out_best_idx, out_best_sc);
}